// round 15
// baseline (speedup 1.0000x reference)
#include <cuda_runtime.h>

// Problem constants (static per reference)
#define NIMG 8
#define CINC 64
#define HH   112
#define WW   112
#define NP   (HH*WW)      // 12544 pixels/patches per image
#define NP4  (NP/4)       // 3136 float4 groups per image
#define COUTC 64
#define DD   576          // CIN*K*K
#define MEM  1025
#define MAXD 1025         // dense-rep capacity (worst case = all bins live)

// Scratch (device globals — no allocation allowed)
__device__ float d_S[NIMG*NP];                  // per-pixel channel sums
__device__ int   d_bins[NIMG*NP];               // raw bin per patch
__device__ int   d_binsd[NIMG*NP];              // DENSE index per patch
__device__ int   d_first[NIMG*MEM];             // first-occurring patch idx per bin
__device__ int   d_dense[NIMG*MEM];             // bin -> dense index map
__device__ int   d_cnt[NIMG];                   // dense count per image
__device__ float d_repd[NIMG*(COUTC/4)*MAXD*4]; // dense reps: [n][c/4][idx][c%4]
__device__ float d_Wt[DD*COUTC];                // transposed weight: Wt[d*64 + c]
__device__ int   d_live[NIMG*MEM];              // compacted list of populated pairs
__device__ int   d_nlive;                       // count of populated bins

// K1: per-pixel channel sum (1 px/thread, MLP-rich) + init tables + weight
// transpose. Per-pixel FP order: sequential c=0..63, single accumulator —
// bit-identical to all validated rounds.
__global__ void k_prep(const float* __restrict__ fmap,
                       const float* __restrict__ weight) {
    int tid   = blockIdx.x * blockDim.x + threadIdx.x;   // [0, NIMG*NP)
    int total = gridDim.x * blockDim.x;

    if (tid == 0) d_nlive = 0;
    if (tid < NIMG) d_cnt[tid] = 0;

    for (int i = tid; i < NIMG*MEM; i += total) d_first[i] = NP;

    for (int i = tid; i < COUTC*DD; i += total) {
        int c = i / DD, d = i - c*DD;
        d_Wt[d*COUTC + c] = weight[i];
    }

    int n = tid / NP, p = tid - n*NP;
    const float* base = fmap + (size_t)n * CINC * NP + p;
    float s = 0.f;
    #pragma unroll 16
    for (int c = 0; c < CINC; c++) s += base[c * NP];
    d_S[tid] = s;
}

// K2: 3x3 box sum (zero-padded) -> quantized bin -> scatter-min first.
// The unique winner per bin claims a dense index and appends to the live list.
__global__ void k_bin() {
    int tid = blockIdx.x * blockDim.x + threadIdx.x;     // [0, NIMG*NP)
    int n = tid / NP, p = tid - n*NP;
    int h = p / WW, w = p - h*WW;
    const float* S = d_S + n*NP;

    float sum = 0.f;
    #pragma unroll
    for (int dy = -1; dy <= 1; dy++) {
        int y = h + dy;
        if (y < 0 || y >= HH) continue;
        const float* Sy = S + y*WW;
        if (w > 0)      sum += Sy[w - 1];
        sum += Sy[w];
        if (w < WW - 1) sum += Sy[w + 1];
    }

    float m = sum / (float)DD;
    int s = (int)(m * 100.0f);             // trunc toward zero == astype(int32)
    int b = s + 512;
    b = b < 0 ? 0 : (b > MEM-1 ? MEM-1 : b);
    d_bins[tid] = b;

    int pair = n*MEM + b;
    int old = atomicMin(&d_first[pair], p);
    if (old == NP) {
        d_dense[pair] = atomicAdd(&d_cnt[n], 1);
        int li = atomicAdd(&d_nlive, 1);
        d_live[li] = pair;
    }
}

// K3: (a) translate raw bins -> dense indices for every pixel (grid-stride);
//     (b) representative GEMVs over the compacted live list, writing the
//     dense-indexed rep table. 296 blocks x 512 threads.
__global__ void __launch_bounds__(512) k_rep(const float* __restrict__ fmap,
                                             const float* __restrict__ bias) {
    int t = threadIdx.x;
    int gtid = blockIdx.x * 512 + t;

    // (a) bins -> dense translation (d_dense complete after k_bin)
    if (gtid < NIMG*NP) {
        int n = gtid / NP;
        d_binsd[gtid] = d_dense[n*MEM + d_bins[gtid]];
    }

    // (b) GEMVs
    __shared__ float sh[DD];
    __shared__ float red[512];
    int nlive = *(volatile int*)&d_nlive;

    for (int i = blockIdx.x; i < nlive; i += gridDim.x) {
        int pair = d_live[i];
        int n = pair / MEM;
        int idx = d_dense[pair];
        int p = d_first[pair];
        int h = p / WW, w = p - h*WW;

        __syncthreads();                    // protect sh/red reuse across iterations
        for (int d = t; d < DD; d += 512) {
            int cin = d / 9, r = d - cin*9;
            int kh = r / 3, kw = r - kh*3;
            int y = h + kh - 1, x = w + kw - 1;
            float v = 0.f;
            if (y >= 0 && y < HH && x >= 0 && x < WW)
                v = fmap[(((size_t)n*CINC + cin)*HH + y)*WW + x];
            sh[d] = v;
        }
        __syncthreads();

        int c = t & 63;            // channel (lane-contiguous -> coalesced Wt loads)
        int g = t >> 6;            // d-group 0..7
        float acc = 0.f;
        int d0 = g * 72;
        #pragma unroll 8
        for (int d = d0; d < d0 + 72; d++)
            acc = fmaf(sh[d], d_Wt[d*COUTC + c], acc);
        red[t] = acc;
        __syncthreads();

        if (t < COUTC) {
            float r = bias[t];
            #pragma unroll
            for (int g2 = 0; g2 < 8; g2++) r += red[t + g2*64];
            // dense quad layout: [n][c/4][idx][c%4]
            d_repd[(((size_t)n*(COUTC/4) + (t >> 2))*MAXD + idx)*4 + (t & 3)] = r;
        }
    }
}

// K4: gather + write with the DENSE rep row (~40 entries, ~640 B) staged in
// shared memory. Grid (13 q-blocks x 128 (n,cq)) = 1664 blocks x 256 threads
// -> full occupancy, near-zero staging cost. One coalesced int4 dense-bins
// load -> 4 LDS gathers (tiny hot region, broadcast-heavy) -> 4 STG.128.
__global__ void __launch_bounds__(256) k_out(float* __restrict__ out) {
    __shared__ float4 srep[MAXD];

    int by = blockIdx.y;
    int n  = by >> 4;                      // 0..7
    int cq = by & 15;                      // 0..15
    int t  = threadIdx.x;

    int cnt = d_cnt[n];
    const float4* rt = (const float4*)d_repd + ((size_t)n*(COUTC/4) + cq)*MAXD;
    for (int i = t; i < cnt; i += 256) srep[i] = rt[i];
    __syncthreads();

    int q = blockIdx.x * 256 + t;
    if (q >= NP4) return;

    int4 b4 = ((const int4*)d_binsd)[n*NP4 + q];
    float4 v0 = srep[b4.x];
    float4 v1 = srep[b4.y];
    float4 v2 = srep[b4.z];
    float4 v3 = srep[b4.w];

    float4* ob = (float4*)out + ((size_t)n*COUTC + cq*4)*NP4 + q;
    ob[0*NP4] = make_float4(v0.x, v1.x, v2.x, v3.x);
    ob[1*NP4] = make_float4(v0.y, v1.y, v2.y, v3.y);
    ob[2*NP4] = make_float4(v0.z, v1.z, v2.z, v3.z);
    ob[3*NP4] = make_float4(v0.w, v1.w, v2.w, v3.w);
}

extern "C" void kernel_launch(void* const* d_in, const int* in_sizes, int n_in,
                              void* d_out, int out_size) {
    const float* fmap   = (const float*)d_in[0];
    const float* weight = (const float*)d_in[1];
    const float* bias   = (const float*)d_in[2];
    float* out = (float*)d_out;

    (void)in_sizes; (void)n_in; (void)out_size;

    k_prep<<<(NIMG*NP + 255)/256, 256>>>(fmap, weight);    // 392 blocks
    k_bin <<<(NIMG*NP + 255)/256, 256>>>();                // 392 blocks
    k_rep <<<296, 512>>>(fmap, bias);                      // translate + GEMVs
    dim3 outGrid((NP4 + 255)/256, NIMG*(COUTC/4));         // 13 x 128 = 1664 blocks
    k_out <<<outGrid, 256>>>(out);
}